// round 7
// baseline (speedup 1.0000x reference)
#include <cuda_runtime.h>
#include <cuda_bf16.h>
#include <math.h>
#include <stdint.h>

// ---------------------------------------------------------------------------
// LinearSelfAttention, Round 7: mma.sync bf16 hi/lo 3-pass GEMMs.
// Block 256x128, 8 warps, 64x64 warp tiles (halves smem reads per MAC),
// 4-stage cp.async ring, fused attn->bf16 split, sincos LUT.
// Shapes: B=4, T=4096, D=1024, H=16, hd=64.
// ---------------------------------------------------------------------------

#define B_   4
#define T_   4096
#define D_   1024
#define H_   16
#define HD_  64
#define M_   (B_ * T_)            // 16384
#define PAIRS (B_ * H_)           // 64
#define NCHUNK 16
#define ROWS_PER_CHUNK (T_ / NCHUNK)
#define GK 1024

// ------------------------- scratch (device globals) ------------------------
__device__ float g_qkv[(size_t)M_ * 3 * D_];           // 192 MB
__device__ float g_qf[(size_t)PAIRS * T_ * HD_];       // 64 MB
__device__ float g_kf[(size_t)PAIRS * T_ * HD_];       // 64 MB
__device__ float g_kvpart[(size_t)NCHUNK * PAIRS * HD_ * HD_];
__device__ float g_kspart[(size_t)NCHUNK * PAIRS * HD_];
__device__ float g_kv[(size_t)PAIRS * HD_ * HD_];
__device__ float g_ksum[(size_t)PAIRS * HD_];
__device__ float g_cost[(size_t)T_ * 32];
__device__ float g_sint[(size_t)T_ * 32];
__device__ __nv_bfloat16 g_ahi[(size_t)M_ * D_];       // 32 MB
__device__ __nv_bfloat16 g_alo[(size_t)M_ * D_];       // 32 MB
__device__ __nv_bfloat16 g_bhi[(size_t)3 * D_ * D_];   // 6 MB
__device__ __nv_bfloat16 g_blo[(size_t)3 * D_ * D_];   // 6 MB

__constant__ float c_invfreq[32] = {
    1.0f, 0.7498942093324559f, 0.5623413251903491f, 0.4216965034285822f,
    0.31622776601683794f, 0.23713737056616552f, 0.1778279410038923f,
    0.13335214321633242f,
    0.1f, 0.07498942093324558f, 0.05623413251903491f, 0.04216965034285822f,
    0.03162277660168379f, 0.023713737056616554f, 0.01778279410038923f,
    0.013335214321633242f,
    0.01f, 0.007498942093324559f, 0.005623413251903491f, 0.004216965034285822f,
    0.0031622776601683794f, 0.0023713737056616554f, 0.001778279410038923f,
    0.0013335214321633242f,
    0.001f, 0.0007498942093324559f, 0.0005623413251903491f,
    0.0004216965034285822f, 0.00031622776601683794f, 0.00023713737056616554f,
    0.0001778279410038923f, 0.00013335214321633243f
};

// ------------------------- PTX helpers --------------------------------------
__device__ __forceinline__ uint32_t smem_u32(const void* p) {
    uint32_t a;
    asm("{ .reg .u64 t; cvta.to.shared.u64 t, %1; cvt.u32.u64 %0, t; }"
        : "=r"(a) : "l"(p));
    return a;
}
__device__ __forceinline__ void cpasync16(uint32_t s, const void* g) {
    asm volatile("cp.async.cg.shared.global [%0], [%1], 16;" :: "r"(s), "l"(g));
}
#define CP_COMMIT() asm volatile("cp.async.commit_group;" ::: "memory")
#define CP_WAIT2()  asm volatile("cp.async.wait_group 2;" ::: "memory")

__device__ __forceinline__ void ldsm4(uint32_t* r, uint32_t addr) {
    asm volatile("ldmatrix.sync.aligned.m8n8.x4.shared.b16 {%0,%1,%2,%3}, [%4];"
        : "=r"(r[0]), "=r"(r[1]), "=r"(r[2]), "=r"(r[3]) : "r"(addr));
}
__device__ __forceinline__ void mma16816(float* d, const uint32_t* a,
                                         const uint32_t* b) {
    asm volatile("mma.sync.aligned.m16n8k16.row.col.f32.bf16.bf16.f32 "
        "{%0,%1,%2,%3}, {%4,%5,%6,%7}, {%8,%9}, {%0,%1,%2,%3};"
        : "+f"(d[0]), "+f"(d[1]), "+f"(d[2]), "+f"(d[3])
        : "r"(a[0]), "r"(a[1]), "r"(a[2]), "r"(a[3]), "r"(b[0]), "r"(b[1]));
}

// ------------------------- MMA GEMM: C = A * B^T ----------------------------
// Block 256x128, 8 warps (4M x 2N), warp tile 64x64, K-step 16, 4 stages.
// RS=24 bf16 (48 B rows): cp.async dst 16B-aligned, ldmatrix conflict-free.
#define RS 24
#define A_ROWS 256
#define OPA (A_ROWS * RS * 2)          // 12288 B (A operand tile)
#define OPB_ (128 * RS * 2)            // 6144 B (B operand tile)
#define OFF_AHI 0
#define OFF_ALO OPA
#define OFF_BHI (2 * OPA)
#define OFF_BLO (2 * OPA + OPB_)
#define STAGE_B (2 * OPA + 2 * OPB_)   // 36864 B per stage
#define NSTAGE 4
#define GEMM_SMEM (NSTAGE * STAGE_B)   // 147456 B -> 1 CTA/SM

__global__ void __launch_bounds__(256)
gemm_mma(const __nv_bfloat16* __restrict__ Ahi, const __nv_bfloat16* __restrict__ Alo,
         const __nv_bfloat16* __restrict__ Bhi, const __nv_bfloat16* __restrict__ Blo,
         float* __restrict__ C, int N)
{
    extern __shared__ __nv_bfloat16 smem[];

    const int tid = threadIdx.x;
    const int l = tid & 31;
    const int w = tid >> 5;
    const int mw = w >> 1;                 // 0..3 (M dir, 64 rows each)
    const int nw = w & 1;                  // 0..1 (N dir, 64 cols each)
    const long rowA0 = (long)blockIdx.y * 256;
    const long rowB0 = (long)blockIdx.x * 128;

    // ---- loader: per stage, 6 x 16B per thread -----------------------------
    const int lrow = tid >> 1;             // 0..127
    const int lhalf = (tid & 1) * 8;       // 0 or 8 (bf16 elems)
    const __nv_bfloat16* gAhi = Ahi + (rowA0 + lrow) * GK + lhalf;
    const __nv_bfloat16* gAlo = Alo + (rowA0 + lrow) * GK + lhalf;
    const __nv_bfloat16* gBhi = Bhi + (rowB0 + lrow) * GK + lhalf;
    const __nv_bfloat16* gBlo = Blo + (rowB0 + lrow) * GK + lhalf;
    const uint32_t sbase = smem_u32(&smem[0]);
    const uint32_t so0 = (uint32_t)((lrow * RS + lhalf) * 2);          // 16B aligned
    const uint32_t so1 = (uint32_t)(((lrow + 128) * RS + lhalf) * 2);

    float acc[4][8][4];
    #pragma unroll
    for (int i = 0; i < 4; i++)
        #pragma unroll
        for (int j = 0; j < 8; j++)
            #pragma unroll
            for (int k = 0; k < 4; k++) acc[i][j][k] = 0.0f;

    // ldmatrix offsets within a stage
    const uint32_t aoffA = (uint32_t)(((mw * 64 + (l & 15)) * RS + (l >> 4) * 8) * 2);
    const uint32_t aoffB = (uint32_t)((((nw * 64 + (l & 7) + ((l >> 4) << 3)) * RS
                                       + ((l >> 3) & 1) * 8)) * 2);

    const int NIT = GK / 16;               // 64

    // ---- prefetch stages 0..2 ---------------------------------------------
    #pragma unroll
    for (int s = 0; s < NSTAGE - 1; s++) {
        const uint32_t dst = sbase + s * STAGE_B;
        const int k0 = s * 16;
        cpasync16(dst + OFF_AHI + so0, gAhi + k0);
        cpasync16(dst + OFF_AHI + so1, gAhi + 128 * GK + k0);
        cpasync16(dst + OFF_ALO + so0, gAlo + k0);
        cpasync16(dst + OFF_ALO + so1, gAlo + 128 * GK + k0);
        cpasync16(dst + OFF_BHI + so0, gBhi + k0);
        cpasync16(dst + OFF_BLO + so0, gBlo + k0);
        CP_COMMIT();
    }

    for (int c = 0; c < NIT; c++) {
        CP_WAIT2();                        // stage c resident
        __syncthreads();                   // slot (c-1)%4 free for refill

        const int pf = c + NSTAGE - 1;
        if (pf < NIT) {
            const uint32_t dst = sbase + (pf & (NSTAGE - 1)) * STAGE_B;
            const int k0 = pf * 16;
            cpasync16(dst + OFF_AHI + so0, gAhi + k0);
            cpasync16(dst + OFF_AHI + so1, gAhi + 128 * GK + k0);
            cpasync16(dst + OFF_ALO + so0, gAlo + k0);
            cpasync16(dst + OFF_ALO + so1, gAlo + 128 * GK + k0);
            cpasync16(dst + OFF_BHI + so0, gBhi + k0);
            cpasync16(dst + OFF_BLO + so0, gBlo + k0);
        }
        CP_COMMIT();                       // unconditional: pending stays == 3

        const uint32_t stb = sbase + (c & (NSTAGE - 1)) * STAGE_B;

        // A fragments for all 4 m-tiles (hi and lo)
        uint32_t ah[4][4], al[4][4];
        #pragma unroll
        for (int mt = 0; mt < 4; mt++) {
            uint32_t ao = stb + aoffA + (uint32_t)(mt * 16 * RS * 2);
            ldsm4(ah[mt], ao + OFF_AHI);
            ldsm4(al[mt], ao + OFF_ALO);
        }

        #pragma unroll
        for (int hf = 0; hf < 2; hf++) {
            uint32_t bh[4][2], bl[4][2];
            #pragma unroll
            for (int nt2 = 0; nt2 < 2; nt2++) {
                uint32_t bo = stb + aoffB
                            + (uint32_t)((hf * 32 + nt2 * 16) * RS * 2);
                uint32_t r[4];
                ldsm4(r, bo + OFF_BHI);
                bh[nt2 * 2][0] = r[0]; bh[nt2 * 2][1] = r[1];
                bh[nt2 * 2 + 1][0] = r[2]; bh[nt2 * 2 + 1][1] = r[3];
                ldsm4(r, bo + OFF_BLO);
                bl[nt2 * 2][0] = r[0]; bl[nt2 * 2][1] = r[1];
                bl[nt2 * 2 + 1][0] = r[2]; bl[nt2 * 2 + 1][1] = r[3];
            }
            #pragma unroll
            for (int mt = 0; mt < 4; mt++)
                #pragma unroll
                for (int nt = 0; nt < 4; nt++) {
                    float* d = acc[mt][hf * 4 + nt];
                    mma16816(d, ah[mt], bh[nt]);
                    mma16816(d, ah[mt], bl[nt]);
                    mma16816(d, al[mt], bh[nt]);
                }
        }
    }

    // ---- epilogue ----------------------------------------------------------
    const long ccol0 = rowB0 + nw * 64 + 2 * (l & 3);
    #pragma unroll
    for (int mt = 0; mt < 4; mt++) {
        const long row = rowA0 + mw * 64 + mt * 16 + (l >> 2);
        #pragma unroll
        for (int nt = 0; nt < 8; nt++) {
            const float* d = acc[mt][nt];
            long col = ccol0 + nt * 8;
            *(float2*)(C + row * N + col) = make_float2(d[0], d[1]);
            *(float2*)(C + (row + 8) * N + col) = make_float2(d[2], d[3]);
        }
    }
}

// ------------------------- fp32 -> bf16 hi/lo split -------------------------
__global__ void __launch_bounds__(256)
split_kernel(const float* __restrict__ src, __nv_bfloat16* __restrict__ hi,
             __nv_bfloat16* __restrict__ lo, int n4)
{
    int i = blockIdx.x * blockDim.x + threadIdx.x;
    if (i >= n4) return;
    float4 v = ((const float4*)src)[i];
    union { __nv_bfloat16 b[4]; uint2 u; } Hv, Lv;
    float f[4] = {v.x, v.y, v.z, v.w};
    #pragma unroll
    for (int j = 0; j < 4; j++) {
        __nv_bfloat16 h = __float2bfloat16(f[j]);
        Hv.b[j] = h;
        Lv.b[j] = __float2bfloat16(f[j] - __bfloat162float(h));
    }
    ((uint2*)hi)[i] = Hv.u;
    ((uint2*)lo)[i] = Lv.u;
}

// ------------------------- sincos table -------------------------------------
__global__ void __launch_bounds__(256)
sincos_table_kernel(float* __restrict__ cost, float* __restrict__ sint)
{
    int idx = blockIdx.x * blockDim.x + threadIdx.x;   // T*32
    int t = idx >> 5;
    int i = idx & 31;
    float s, c;
    sincosf((float)t * c_invfreq[i], &s, &c);
    cost[idx] = c;
    sint[idx] = s;
}

// ------------------------- RoPE + feature map -------------------------------
__global__ void __launch_bounds__(256)
rope_feat_kernel(const float* __restrict__ qkv,
                 const float* __restrict__ cost, const float* __restrict__ sint,
                 float* __restrict__ qf, float* __restrict__ kf)
{
    int idx = blockIdx.x * blockDim.x + threadIdx.x;
    int i = idx & 31;
    int t = (idx >> 5) & (T_ - 1);
    int pair = idx >> 17;
    int b = pair >> 4;
    int h = pair & 15;

    size_t basei = ((size_t)(b * T_ + t)) * (3 * D_) + h * HD_;
    float qe = qkv[basei + i];
    float qo = qkv[basei + i + 32];
    float ke = qkv[basei + D_ + i];
    float ko = qkv[basei + D_ + i + 32];

    float c = cost[t * 32 + i];
    float s = sint[t * 32 + i];

    float qre = qe * c - qo * s;
    float qro = qe * s + qo * c;
    float kre = ke * c - ko * s;
    float kro = ke * s + ko * c;

    const float scale = 0.125f;
    qre *= scale; qro *= scale;

    float fqe = qre > 0.0f ? qre + 1.0f : expm1f(qre) + 1.0f;
    float fqo = qro > 0.0f ? qro + 1.0f : expm1f(qro) + 1.0f;
    float fke = kre > 0.0f ? kre + 1.0f : expm1f(kre) + 1.0f;
    float fko = kro > 0.0f ? kro + 1.0f : expm1f(kro) + 1.0f;

    size_t ob = ((size_t)pair * T_ + t) * HD_;
    qf[ob + i]      = fqe;
    qf[ob + i + 32] = fqo;
    kf[ob + i]      = fke;
    kf[ob + i + 32] = fko;
}

// ------------------------- kv = K^T V, k_sum (partials) ---------------------
__global__ void __launch_bounds__(256)
kv_ksum_kernel(const float* __restrict__ kf, const float* __restrict__ qkv,
               float* __restrict__ kvpart, float* __restrict__ kspart)
{
    __shared__ float ks[32][64];
    __shared__ float vs[32][64];

    const int pair = blockIdx.y;
    const int chunk = blockIdx.x;
    const int b = pair >> 4;
    const int h = pair & 15;
    const int tid = threadIdx.x;
    const int tx = tid & 15;
    const int ty = tid >> 4;

    const float* kbase = kf + ((size_t)pair * T_ + chunk * ROWS_PER_CHUNK) * HD_;
    const float* vbase = qkv + ((size_t)(b * T_ + chunk * ROWS_PER_CHUNK)) * (3 * D_)
                         + 2 * D_ + h * HD_;

    float acc[4][4];
    #pragma unroll
    for (int i = 0; i < 4; i++)
        #pragma unroll
        for (int j = 0; j < 4; j++) acc[i][j] = 0.0f;
    float ksl[4] = {0.0f, 0.0f, 0.0f, 0.0f};

    for (int tile = 0; tile < ROWS_PER_CHUNK / 32; tile++) {
        #pragma unroll
        for (int lp = 0; lp < 2; lp++) {
            int fi = tid + lp * 256;
            int row = fi >> 4;
            int c4 = (fi & 15) * 4;
            *(float4*)&ks[row][c4] =
                *(const float4*)(kbase + (size_t)(tile * 32 + row) * HD_ + c4);
            *(float4*)&vs[row][c4] =
                *(const float4*)(vbase + (size_t)(tile * 32 + row) * (3 * D_) + c4);
        }
        __syncthreads();

        #pragma unroll
        for (int r = 0; r < 32; r++) {
            float ka[4], va[4];
            *(float4*)ka = *(const float4*)&ks[r][ty * 4];
            *(float4*)va = *(const float4*)&vs[r][tx * 4];
            #pragma unroll
            for (int i = 0; i < 4; i++)
                #pragma unroll
                for (int j = 0; j < 4; j++)
                    acc[i][j] = fmaf(ka[i], va[j], acc[i][j]);
            if (ty == 0) {
                #pragma unroll
                for (int j = 0; j < 4; j++)
                    ksl[j] += ks[r][tx * 4 + j];
            }
        }
        __syncthreads();
    }

    float* kvp = kvpart + (size_t)chunk * (PAIRS * HD_ * HD_) + (size_t)pair * HD_ * HD_;
    #pragma unroll
    for (int i = 0; i < 4; i++)
        #pragma unroll
        for (int j = 0; j < 4; j++)
            kvp[(ty * 4 + i) * HD_ + tx * 4 + j] = acc[i][j];
    if (ty == 0) {
        float* ksp = kspart + (size_t)chunk * (PAIRS * HD_) + pair * HD_;
        #pragma unroll
        for (int j = 0; j < 4; j++) ksp[tx * 4 + j] = ksl[j];
    }
}

__global__ void __launch_bounds__(256)
reduce_kv_kernel(const float* __restrict__ kvpart, const float* __restrict__ kspart,
                 float* __restrict__ kv, float* __restrict__ ksum)
{
    int i = blockIdx.x * blockDim.x + threadIdx.x;
    float s = 0.0f;
    #pragma unroll
    for (int c = 0; c < NCHUNK; c++)
        s += kvpart[(size_t)c * (PAIRS * HD_ * HD_) + i];
    kv[i] = s;
    if (i < PAIRS * HD_) {
        float s2 = 0.0f;
        #pragma unroll
        for (int c = 0; c < NCHUNK; c++)
            s2 += kspart[(size_t)c * (PAIRS * HD_) + i];
        ksum[i] = s2;
    }
}

// ---------------- out = (Q kv)/denom, fused bf16 hi/lo output ---------------
__global__ void __launch_bounds__(256)
attn_out_kernel(const float* __restrict__ qf, const float* __restrict__ kv,
                const float* __restrict__ ksum,
                __nv_bfloat16* __restrict__ ahi, __nv_bfloat16* __restrict__ alo)
{
    __shared__ float kv_s[HD_][HD_];
    __shared__ float q_s[32][HD_];
    __shared__ float ksum_s[HD_];

    const int pair = blockIdx.y;
    const int t0 = blockIdx.x * 32;
    const int b = pair >> 4;
    const int h = pair & 15;
    const int tid = threadIdx.x;
    const int row = tid >> 3;
    const int tx = tid & 7;

    const float4* kvp = (const float4*)(kv + (size_t)pair * HD_ * HD_);
    #pragma unroll
    for (int lp = 0; lp < 4; lp++)
        ((float4*)kv_s)[tid + lp * 256] = kvp[tid + lp * 256];
    if (tid < 16)
        ((float4*)ksum_s)[tid] = ((const float4*)(ksum + pair * HD_))[tid];
    const float4* qp = (const float4*)(qf + ((size_t)pair * T_ + t0) * HD_);
    #pragma unroll
    for (int lp = 0; lp < 2; lp++)
        ((float4*)q_s)[tid + lp * 256] = qp[tid + lp * 256];
    __syncthreads();

    float acc[8] = {0, 0, 0, 0, 0, 0, 0, 0};
    float den = 0.0f;
    #pragma unroll
    for (int d = 0; d < HD_; d++) {
        float qd = q_s[row][d];
        den = fmaf(qd, ksum_s[d], den);
        float4 k0 = *(const float4*)&kv_s[d][tx * 8];
        float4 k1 = *(const float4*)&kv_s[d][tx * 8 + 4];
        acc[0] = fmaf(qd, k0.x, acc[0]);
        acc[1] = fmaf(qd, k0.y, acc[1]);
        acc[2] = fmaf(qd, k0.z, acc[2]);
        acc[3] = fmaf(qd, k0.w, acc[3]);
        acc[4] = fmaf(qd, k1.x, acc[4]);
        acc[5] = fmaf(qd, k1.y, acc[5]);
        acc[6] = fmaf(qd, k1.z, acc[6]);
        acc[7] = fmaf(qd, k1.w, acc[7]);
    }
    float inv = 1.0f / fmaxf(den, 1e-6f);

    union { __nv_bfloat16 b[8]; uint4 u; } Hv, Lv;
    #pragma unroll
    for (int j = 0; j < 8; j++) {
        float v = acc[j] * inv;
        __nv_bfloat16 hh = __float2bfloat16(v);
        Hv.b[j] = hh;
        Lv.b[j] = __float2bfloat16(v - __bfloat162float(hh));
    }
    size_t off = ((size_t)(b * T_ + t0 + row)) * D_ + h * HD_ + tx * 8;
    *(uint4*)(ahi + off) = Hv.u;
    *(uint4*)(alo + off) = Lv.u;
}

// ------------------------- launch ------------------------------------------
static float* sym_addr_f(const void* symbol)
{
    void* p = nullptr;
    cudaGetSymbolAddress(&p, symbol);
    return (float*)p;
}
static __nv_bfloat16* sym_addr_b(const void* symbol)
{
    void* p = nullptr;
    cudaGetSymbolAddress(&p, symbol);
    return (__nv_bfloat16*)p;
}

extern "C" void kernel_launch(void* const* d_in, const int* in_sizes, int n_in,
                              void* d_out, int out_size)
{
    (void)in_sizes; (void)n_in; (void)out_size;
    const float* x     = (const float*)d_in[0];   // [B,T,D]
    const float* w_qkv = (const float*)d_in[1];   // [3D,D]
    const float* w_out = (const float*)d_in[2];   // [D,D]
    float* out = (float*)d_out;                   // [B,T,D]

    float* qkv   = sym_addr_f(g_qkv);
    float* qf    = sym_addr_f(g_qf);
    float* kf    = sym_addr_f(g_kf);
    float* kvprt = sym_addr_f(g_kvpart);
    float* ksprt = sym_addr_f(g_kspart);
    float* kv    = sym_addr_f(g_kv);
    float* ksum  = sym_addr_f(g_ksum);
    float* cost  = sym_addr_f(g_cost);
    float* sint  = sym_addr_f(g_sint);
    __nv_bfloat16* ahi = sym_addr_b(g_ahi);
    __nv_bfloat16* alo = sym_addr_b(g_alo);
    __nv_bfloat16* bhi = sym_addr_b(g_bhi);
    __nv_bfloat16* blo = sym_addr_b(g_blo);

    cudaFuncSetAttribute(gemm_mma, cudaFuncAttributeMaxDynamicSharedMemorySize,
                         GEMM_SMEM);

    // 0) sincos LUT
    sincos_table_kernel<<<(T_ * 32) / 256, 256>>>(cost, sint);

    // 1) split x and w_qkv into bf16 hi/lo
    split_kernel<<<(M_ * D_ / 4) / 256, 256>>>(x, ahi, alo, M_ * D_ / 4);
    split_kernel<<<(3 * D_ * D_ / 4) / 256, 256>>>(w_qkv, bhi, blo, 3 * D_ * D_ / 4);

    // 2) qkv = x @ w_qkv^T  [16384, 3072]
    gemm_mma<<<dim3(3 * D_ / 128, M_ / 256), 256, GEMM_SMEM>>>(
        ahi, alo, bhi, blo, qkv, 3 * D_);

    // 3) RoPE + ELU feature map
    rope_feat_kernel<<<(PAIRS * T_ * 32) / 256, 256>>>(qkv, cost, sint, qf, kf);

    // 4) kv = K^T V and k_sum
    kv_ksum_kernel<<<dim3(NCHUNK, PAIRS), 256>>>(kf, qkv, kvprt, ksprt);
    reduce_kv_kernel<<<(PAIRS * HD_ * HD_) / 256, 256>>>(kvprt, ksprt, kv, ksum);

    // 5) out_head = (Q kv)/denom -> bf16 hi/lo directly (A of GEMM2)
    attn_out_kernel<<<dim3(T_ / 32, PAIRS), 256>>>(qf, kv, ksum, ahi, alo);

    // 6) split w_out, then out = attn @ w_out^T  [16384, 1024]
    split_kernel<<<(D_ * D_ / 4) / 256, 256>>>(w_out, bhi, blo, D_ * D_ / 4);
    gemm_mma<<<dim3(D_ / 128, M_ / 256), 256, GEMM_SMEM>>>(
        ahi, alo, bhi, blo, out, D_);
}

// round 8
// speedup vs baseline: 1.2337x; 1.2337x over previous
#include <cuda_runtime.h>
#include <cuda_bf16.h>
#include <math.h>
#include <stdint.h>

// ---------------------------------------------------------------------------
// LinearSelfAttention, Round 8: mma.sync bf16 hi/lo 3-pass GEMMs.
// Block 128x128 (8 warps, 32x64 warp tiles, 128 regs, 2 CTAs/SM),
// k32 stages with XOR-swizzled 64B rows, 3-stage cp.async ring
// (32 barrier epochs), fused attn->bf16 split, sincos LUT.
// ---------------------------------------------------------------------------

#define B_   4
#define T_   4096
#define D_   1024
#define H_   16
#define HD_  64
#define M_   (B_ * T_)            // 16384
#define PAIRS (B_ * H_)           // 64
#define NCHUNK 16
#define ROWS_PER_CHUNK (T_ / NCHUNK)
#define GK 1024

// ------------------------- scratch (device globals) ------------------------
__device__ float g_qkv[(size_t)M_ * 3 * D_];
__device__ float g_qf[(size_t)PAIRS * T_ * HD_];
__device__ float g_kf[(size_t)PAIRS * T_ * HD_];
__device__ float g_kvpart[(size_t)NCHUNK * PAIRS * HD_ * HD_];
__device__ float g_kspart[(size_t)NCHUNK * PAIRS * HD_];
__device__ float g_kv[(size_t)PAIRS * HD_ * HD_];
__device__ float g_ksum[(size_t)PAIRS * HD_];
__device__ float g_cost[(size_t)T_ * 32];
__device__ float g_sint[(size_t)T_ * 32];
__device__ __nv_bfloat16 g_ahi[(size_t)M_ * D_];
__device__ __nv_bfloat16 g_alo[(size_t)M_ * D_];
__device__ __nv_bfloat16 g_bhi[(size_t)3 * D_ * D_];
__device__ __nv_bfloat16 g_blo[(size_t)3 * D_ * D_];

__constant__ float c_invfreq[32] = {
    1.0f, 0.7498942093324559f, 0.5623413251903491f, 0.4216965034285822f,
    0.31622776601683794f, 0.23713737056616552f, 0.1778279410038923f,
    0.13335214321633242f,
    0.1f, 0.07498942093324558f, 0.05623413251903491f, 0.04216965034285822f,
    0.03162277660168379f, 0.023713737056616554f, 0.01778279410038923f,
    0.013335214321633242f,
    0.01f, 0.007498942093324559f, 0.005623413251903491f, 0.004216965034285822f,
    0.0031622776601683794f, 0.0023713737056616554f, 0.001778279410038923f,
    0.0013335214321633242f,
    0.001f, 0.0007498942093324559f, 0.0005623413251903491f,
    0.0004216965034285822f, 0.00031622776601683794f, 0.00023713737056616554f,
    0.0001778279410038923f, 0.00013335214321633243f
};

// ------------------------- PTX helpers --------------------------------------
__device__ __forceinline__ uint32_t smem_u32(const void* p) {
    uint32_t a;
    asm("{ .reg .u64 t; cvta.to.shared.u64 t, %1; cvt.u32.u64 %0, t; }"
        : "=r"(a) : "l"(p));
    return a;
}
__device__ __forceinline__ void cpasync16(uint32_t s, const void* g) {
    asm volatile("cp.async.cg.shared.global [%0], [%1], 16;" :: "r"(s), "l"(g));
}
#define CP_COMMIT() asm volatile("cp.async.commit_group;" ::: "memory")
#define CP_WAIT1()  asm volatile("cp.async.wait_group 1;" ::: "memory")

__device__ __forceinline__ void ldsm4(uint32_t* r, uint32_t addr) {
    asm volatile("ldmatrix.sync.aligned.m8n8.x4.shared.b16 {%0,%1,%2,%3}, [%4];"
        : "=r"(r[0]), "=r"(r[1]), "=r"(r[2]), "=r"(r[3]) : "r"(addr));
}
__device__ __forceinline__ void mma16816(float* d, const uint32_t* a,
                                         const uint32_t* b) {
    asm volatile("mma.sync.aligned.m16n8k16.row.col.f32.bf16.bf16.f32 "
        "{%0,%1,%2,%3}, {%4,%5,%6,%7}, {%8,%9}, {%0,%1,%2,%3};"
        : "+f"(d[0]), "+f"(d[1]), "+f"(d[2]), "+f"(d[3])
        : "r"(a[0]), "r"(a[1]), "r"(a[2]), "r"(a[3]), "r"(b[0]), "r"(b[1]));
}

// ------------------------- MMA GEMM: C = A * B^T ----------------------------
// Block 128x128, 8 warps (4M x 2N), warp tile 32x64, k32 stages, 3-stage ring.
// Rows are 64 B (32 bf16), chunk-swizzled: phys_chunk = chunk ^ ((row>>1)&3).
#define OPB_ (128 * 64)               // 8192 B per operand tile
#define OFF_AHI 0
#define OFF_ALO OPB_
#define OFF_BHI (2 * OPB_)
#define OFF_BLO (3 * OPB_)
#define STAGE_B (4 * OPB_)            // 32768 B per stage
#define NSTAGE 3
#define GEMM_SMEM (NSTAGE * STAGE_B)  // 98304 B -> 2 CTAs/SM

__global__ void __launch_bounds__(256, 2)
gemm_mma(const __nv_bfloat16* __restrict__ Ahi, const __nv_bfloat16* __restrict__ Alo,
         const __nv_bfloat16* __restrict__ Bhi, const __nv_bfloat16* __restrict__ Blo,
         float* __restrict__ C, int N)
{
    extern __shared__ __nv_bfloat16 smem[];

    const int tid = threadIdx.x;
    const int l = tid & 31;
    const int w = tid >> 5;
    const int mw = w >> 1;                 // 0..3
    const int nw = w & 1;                  // 0..1
    const long rowA0 = (long)blockIdx.y * 128;
    const long rowB0 = (long)blockIdx.x * 128;

    // ---- loader: 2 chunks (16B) per operand per thread per stage ----------
    const int lrow = tid >> 1;             // 0..127
    const int lc0 = (tid & 1) * 2;         // chunk 0 or 2
    const int lsw = (lrow >> 1) & 3;
    const uint32_t ld0 = (uint32_t)(lrow * 64 + ((lc0 ^ lsw) << 4));
    const uint32_t ld1 = (uint32_t)(lrow * 64 + (((lc0 + 1) ^ lsw) << 4));
    const int le0 = lc0 * 8;               // global elem offset of chunk lc0
    const __nv_bfloat16* gAhi = Ahi + (rowA0 + lrow) * GK + le0;
    const __nv_bfloat16* gAlo = Alo + (rowA0 + lrow) * GK + le0;
    const __nv_bfloat16* gBhi = Bhi + (rowB0 + lrow) * GK + le0;
    const __nv_bfloat16* gBlo = Blo + (rowB0 + lrow) * GK + le0;
    const uint32_t sbase = smem_u32(&smem[0]);

    float acc[2][8][4];
    #pragma unroll
    for (int i = 0; i < 2; i++)
        #pragma unroll
        for (int j = 0; j < 8; j++)
            #pragma unroll
            for (int k = 0; k < 4; k++) acc[i][j][k] = 0.0f;

    // ldmatrix lane-row bases (swizzle const is position-independent since all
    // tile offsets are multiples of 16 rows -> (row>>1)&3 unchanged)
    const int rA = mw * 32 + (l & 15);
    const uint32_t bA = (uint32_t)(rA * 64);
    const uint32_t sA = (uint32_t)((rA >> 1) & 3);
    const int chA0 = (l >> 4);             // + ksub*2
    const int rB = nw * 64 + (l & 7) + ((l >> 4) << 3);
    const uint32_t bB = (uint32_t)(rB * 64);
    const uint32_t sB = (uint32_t)((rB >> 1) & 3);
    const int chB0 = ((l >> 3) & 1);       // + ksub*2

    const int NIT = GK / 32;               // 32

    // ---- prologue: prefetch stages 0,1 ------------------------------------
    #pragma unroll
    for (int s = 0; s < 2; s++) {
        const uint32_t dst = sbase + s * STAGE_B;
        const int k0 = s * 32;
        cpasync16(dst + OFF_AHI + ld0, gAhi + k0);
        cpasync16(dst + OFF_AHI + ld1, gAhi + k0 + 8);
        cpasync16(dst + OFF_ALO + ld0, gAlo + k0);
        cpasync16(dst + OFF_ALO + ld1, gAlo + k0 + 8);
        cpasync16(dst + OFF_BHI + ld0, gBhi + k0);
        cpasync16(dst + OFF_BHI + ld1, gBhi + k0 + 8);
        cpasync16(dst + OFF_BLO + ld0, gBlo + k0);
        cpasync16(dst + OFF_BLO + ld1, gBlo + k0 + 8);
        CP_COMMIT();
    }

    int sc = 0, sp = 2;                    // current slot, prefetch slot
    for (int c = 0; c < NIT; c++) {
        CP_WAIT1();                        // stage c resident
        __syncthreads();                   // visible to all; slot sp safe

        if (c + 2 < NIT) {
            const uint32_t dst = sbase + sp * STAGE_B;
            const int k0 = (c + 2) * 32;
            cpasync16(dst + OFF_AHI + ld0, gAhi + k0);
            cpasync16(dst + OFF_AHI + ld1, gAhi + k0 + 8);
            cpasync16(dst + OFF_ALO + ld0, gAlo + k0);
            cpasync16(dst + OFF_ALO + ld1, gAlo + k0 + 8);
            cpasync16(dst + OFF_BHI + ld0, gBhi + k0);
            cpasync16(dst + OFF_BHI + ld1, gBhi + k0 + 8);
            cpasync16(dst + OFF_BLO + ld0, gBlo + k0);
            cpasync16(dst + OFF_BLO + ld1, gBlo + k0 + 8);
        }
        CP_COMMIT();                       // unconditional: pending stays 2

        const uint32_t stb = sbase + sc * STAGE_B;

        #pragma unroll
        for (int ksub = 0; ksub < 2; ksub++) {
            const uint32_t cA = (uint32_t)(ksub * 2 + chA0);
            const uint32_t cB = (uint32_t)(ksub * 2 + chB0);
            const uint32_t aA = stb + bA + ((cA ^ sA) << 4);
            const uint32_t aB = stb + bB + ((cB ^ sB) << 4);

            uint32_t ah[2][4], al[2][4];
            #pragma unroll
            for (int mt = 0; mt < 2; mt++) {
                uint32_t ao = aA + (uint32_t)(mt * 16 * 64);
                ldsm4(ah[mt], ao + OFF_AHI);
                ldsm4(al[mt], ao + OFF_ALO);
            }

            #pragma unroll
            for (int hf = 0; hf < 2; hf++) {
                uint32_t bh[4][2], bl[4][2];
                #pragma unroll
                for (int nt2 = 0; nt2 < 2; nt2++) {
                    uint32_t bo = aB + (uint32_t)((hf * 32 + nt2 * 16) * 64);
                    uint32_t r[4];
                    ldsm4(r, bo + OFF_BHI);
                    bh[nt2 * 2][0] = r[0]; bh[nt2 * 2][1] = r[1];
                    bh[nt2 * 2 + 1][0] = r[2]; bh[nt2 * 2 + 1][1] = r[3];
                    ldsm4(r, bo + OFF_BLO);
                    bl[nt2 * 2][0] = r[0]; bl[nt2 * 2][1] = r[1];
                    bl[nt2 * 2 + 1][0] = r[2]; bl[nt2 * 2 + 1][1] = r[3];
                }
                #pragma unroll
                for (int mt = 0; mt < 2; mt++)
                    #pragma unroll
                    for (int nt = 0; nt < 4; nt++) {
                        float* d = acc[mt][hf * 4 + nt];
                        mma16816(d, ah[mt], bh[nt]);
                        mma16816(d, ah[mt], bl[nt]);
                        mma16816(d, al[mt], bh[nt]);
                    }
            }
        }
        sc++; if (sc == NSTAGE) sc = 0;
        sp++; if (sp == NSTAGE) sp = 0;
    }

    // ---- epilogue ----------------------------------------------------------
    const long ccol0 = rowB0 + nw * 64 + 2 * (l & 3);
    #pragma unroll
    for (int mt = 0; mt < 2; mt++) {
        const long row = rowA0 + mw * 32 + mt * 16 + (l >> 2);
        #pragma unroll
        for (int nt = 0; nt < 8; nt++) {
            const float* d = acc[mt][nt];
            long col = ccol0 + nt * 8;
            *(float2*)(C + row * N + col) = make_float2(d[0], d[1]);
            *(float2*)(C + (row + 8) * N + col) = make_float2(d[2], d[3]);
        }
    }
}

// ------------------------- fp32 -> bf16 hi/lo split -------------------------
__global__ void __launch_bounds__(256)
split_kernel(const float* __restrict__ src, __nv_bfloat16* __restrict__ hi,
             __nv_bfloat16* __restrict__ lo, int n4)
{
    int i = blockIdx.x * blockDim.x + threadIdx.x;
    if (i >= n4) return;
    float4 v = ((const float4*)src)[i];
    union { __nv_bfloat16 b[4]; uint2 u; } Hv, Lv;
    float f[4] = {v.x, v.y, v.z, v.w};
    #pragma unroll
    for (int j = 0; j < 4; j++) {
        __nv_bfloat16 h = __float2bfloat16(f[j]);
        Hv.b[j] = h;
        Lv.b[j] = __float2bfloat16(f[j] - __bfloat162float(h));
    }
    ((uint2*)hi)[i] = Hv.u;
    ((uint2*)lo)[i] = Lv.u;
}

// ------------------------- sincos table -------------------------------------
__global__ void __launch_bounds__(256)
sincos_table_kernel(float* __restrict__ cost, float* __restrict__ sint)
{
    int idx = blockIdx.x * blockDim.x + threadIdx.x;   // T*32
    int t = idx >> 5;
    int i = idx & 31;
    float s, c;
    sincosf((float)t * c_invfreq[i], &s, &c);
    cost[idx] = c;
    sint[idx] = s;
}

// ------------------------- RoPE + feature map -------------------------------
__global__ void __launch_bounds__(256)
rope_feat_kernel(const float* __restrict__ qkv,
                 const float* __restrict__ cost, const float* __restrict__ sint,
                 float* __restrict__ qf, float* __restrict__ kf)
{
    int idx = blockIdx.x * blockDim.x + threadIdx.x;
    int i = idx & 31;
    int t = (idx >> 5) & (T_ - 1);
    int pair = idx >> 17;
    int b = pair >> 4;
    int h = pair & 15;

    size_t basei = ((size_t)(b * T_ + t)) * (3 * D_) + h * HD_;
    float qe = qkv[basei + i];
    float qo = qkv[basei + i + 32];
    float ke = qkv[basei + D_ + i];
    float ko = qkv[basei + D_ + i + 32];

    float c = cost[t * 32 + i];
    float s = sint[t * 32 + i];

    float qre = qe * c - qo * s;
    float qro = qe * s + qo * c;
    float kre = ke * c - ko * s;
    float kro = ke * s + ko * c;

    const float scale = 0.125f;
    qre *= scale; qro *= scale;

    float fqe = qre > 0.0f ? qre + 1.0f : expm1f(qre) + 1.0f;
    float fqo = qro > 0.0f ? qro + 1.0f : expm1f(qro) + 1.0f;
    float fke = kre > 0.0f ? kre + 1.0f : expm1f(kre) + 1.0f;
    float fko = kro > 0.0f ? kro + 1.0f : expm1f(kro) + 1.0f;

    size_t ob = ((size_t)pair * T_ + t) * HD_;
    qf[ob + i]      = fqe;
    qf[ob + i + 32] = fqo;
    kf[ob + i]      = fke;
    kf[ob + i + 32] = fko;
}

// ------------------------- kv = K^T V, k_sum (partials) ---------------------
__global__ void __launch_bounds__(256)
kv_ksum_kernel(const float* __restrict__ kf, const float* __restrict__ qkv,
               float* __restrict__ kvpart, float* __restrict__ kspart)
{
    __shared__ float ks[32][64];
    __shared__ float vs[32][64];

    const int pair = blockIdx.y;
    const int chunk = blockIdx.x;
    const int b = pair >> 4;
    const int h = pair & 15;
    const int tid = threadIdx.x;
    const int tx = tid & 15;
    const int ty = tid >> 4;

    const float* kbase = kf + ((size_t)pair * T_ + chunk * ROWS_PER_CHUNK) * HD_;
    const float* vbase = qkv + ((size_t)(b * T_ + chunk * ROWS_PER_CHUNK)) * (3 * D_)
                         + 2 * D_ + h * HD_;

    float acc[4][4];
    #pragma unroll
    for (int i = 0; i < 4; i++)
        #pragma unroll
        for (int j = 0; j < 4; j++) acc[i][j] = 0.0f;
    float ksl[4] = {0.0f, 0.0f, 0.0f, 0.0f};

    for (int tile = 0; tile < ROWS_PER_CHUNK / 32; tile++) {
        #pragma unroll
        for (int lp = 0; lp < 2; lp++) {
            int fi = tid + lp * 256;
            int row = fi >> 4;
            int c4 = (fi & 15) * 4;
            *(float4*)&ks[row][c4] =
                *(const float4*)(kbase + (size_t)(tile * 32 + row) * HD_ + c4);
            *(float4*)&vs[row][c4] =
                *(const float4*)(vbase + (size_t)(tile * 32 + row) * (3 * D_) + c4);
        }
        __syncthreads();

        #pragma unroll
        for (int r = 0; r < 32; r++) {
            float ka[4], va[4];
            *(float4*)ka = *(const float4*)&ks[r][ty * 4];
            *(float4*)va = *(const float4*)&vs[r][tx * 4];
            #pragma unroll
            for (int i = 0; i < 4; i++)
                #pragma unroll
                for (int j = 0; j < 4; j++)
                    acc[i][j] = fmaf(ka[i], va[j], acc[i][j]);
            if (ty == 0) {
                #pragma unroll
                for (int j = 0; j < 4; j++)
                    ksl[j] += ks[r][tx * 4 + j];
            }
        }
        __syncthreads();
    }

    float* kvp = kvpart + (size_t)chunk * (PAIRS * HD_ * HD_) + (size_t)pair * HD_ * HD_;
    #pragma unroll
    for (int i = 0; i < 4; i++)
        #pragma unroll
        for (int j = 0; j < 4; j++)
            kvp[(ty * 4 + i) * HD_ + tx * 4 + j] = acc[i][j];
    if (ty == 0) {
        float* ksp = kspart + (size_t)chunk * (PAIRS * HD_) + pair * HD_;
        #pragma unroll
        for (int j = 0; j < 4; j++) ksp[tx * 4 + j] = ksl[j];
    }
}

__global__ void __launch_bounds__(256)
reduce_kv_kernel(const float* __restrict__ kvpart, const float* __restrict__ kspart,
                 float* __restrict__ kv, float* __restrict__ ksum)
{
    int i = blockIdx.x * blockDim.x + threadIdx.x;
    float s = 0.0f;
    #pragma unroll
    for (int c = 0; c < NCHUNK; c++)
        s += kvpart[(size_t)c * (PAIRS * HD_ * HD_) + i];
    kv[i] = s;
    if (i < PAIRS * HD_) {
        float s2 = 0.0f;
        #pragma unroll
        for (int c = 0; c < NCHUNK; c++)
            s2 += kspart[(size_t)c * (PAIRS * HD_) + i];
        ksum[i] = s2;
    }
}

// ---------------- out = (Q kv)/denom, fused bf16 hi/lo output ---------------
__global__ void __launch_bounds__(256)
attn_out_kernel(const float* __restrict__ qf, const float* __restrict__ kv,
                const float* __restrict__ ksum,
                __nv_bfloat16* __restrict__ ahi, __nv_bfloat16* __restrict__ alo)
{
    __shared__ float kv_s[HD_][HD_];
    __shared__ float q_s[32][HD_];
    __shared__ float ksum_s[HD_];

    const int pair = blockIdx.y;
    const int t0 = blockIdx.x * 32;
    const int b = pair >> 4;
    const int h = pair & 15;
    const int tid = threadIdx.x;
    const int row = tid >> 3;
    const int tx = tid & 7;

    const float4* kvp = (const float4*)(kv + (size_t)pair * HD_ * HD_);
    #pragma unroll
    for (int lp = 0; lp < 4; lp++)
        ((float4*)kv_s)[tid + lp * 256] = kvp[tid + lp * 256];
    if (tid < 16)
        ((float4*)ksum_s)[tid] = ((const float4*)(ksum + pair * HD_))[tid];
    const float4* qp = (const float4*)(qf + ((size_t)pair * T_ + t0) * HD_);
    #pragma unroll
    for (int lp = 0; lp < 2; lp++)
        ((float4*)q_s)[tid + lp * 256] = qp[tid + lp * 256];
    __syncthreads();

    float acc[8] = {0, 0, 0, 0, 0, 0, 0, 0};
    float den = 0.0f;
    #pragma unroll
    for (int d = 0; d < HD_; d++) {
        float qd = q_s[row][d];
        den = fmaf(qd, ksum_s[d], den);
        float4 k0 = *(const float4*)&kv_s[d][tx * 8];
        float4 k1 = *(const float4*)&kv_s[d][tx * 8 + 4];
        acc[0] = fmaf(qd, k0.x, acc[0]);
        acc[1] = fmaf(qd, k0.y, acc[1]);
        acc[2] = fmaf(qd, k0.z, acc[2]);
        acc[3] = fmaf(qd, k0.w, acc[3]);
        acc[4] = fmaf(qd, k1.x, acc[4]);
        acc[5] = fmaf(qd, k1.y, acc[5]);
        acc[6] = fmaf(qd, k1.z, acc[6]);
        acc[7] = fmaf(qd, k1.w, acc[7]);
    }
    float inv = 1.0f / fmaxf(den, 1e-6f);

    union { __nv_bfloat16 b[8]; uint4 u; } Hv, Lv;
    #pragma unroll
    for (int j = 0; j < 8; j++) {
        float v = acc[j] * inv;
        __nv_bfloat16 hh = __float2bfloat16(v);
        Hv.b[j] = hh;
        Lv.b[j] = __float2bfloat16(v - __bfloat162float(hh));
    }
    size_t off = ((size_t)(b * T_ + t0 + row)) * D_ + h * HD_ + tx * 8;
    *(uint4*)(ahi + off) = Hv.u;
    *(uint4*)(alo + off) = Lv.u;
}

// ------------------------- launch ------------------------------------------
static float* sym_addr_f(const void* symbol)
{
    void* p = nullptr;
    cudaGetSymbolAddress(&p, symbol);
    return (float*)p;
}
static __nv_bfloat16* sym_addr_b(const void* symbol)
{
    void* p = nullptr;
    cudaGetSymbolAddress(&p, symbol);
    return (__nv_bfloat16*)p;
}

extern "C" void kernel_launch(void* const* d_in, const int* in_sizes, int n_in,
                              void* d_out, int out_size)
{
    (void)in_sizes; (void)n_in; (void)out_size;
    const float* x     = (const float*)d_in[0];   // [B,T,D]
    const float* w_qkv = (const float*)d_in[1];   // [3D,D]
    const float* w_out = (const float*)d_in[2];   // [D,D]
    float* out = (float*)d_out;                   // [B,T,D]

    float* qkv   = sym_addr_f(g_qkv);
    float* qf    = sym_addr_f(g_qf);
    float* kf    = sym_addr_f(g_kf);
    float* kvprt = sym_addr_f(g_kvpart);
    float* ksprt = sym_addr_f(g_kspart);
    float* kv    = sym_addr_f(g_kv);
    float* ksum  = sym_addr_f(g_ksum);
    float* cost  = sym_addr_f(g_cost);
    float* sint  = sym_addr_f(g_sint);
    __nv_bfloat16* ahi = sym_addr_b(g_ahi);
    __nv_bfloat16* alo = sym_addr_b(g_alo);
    __nv_bfloat16* bhi = sym_addr_b(g_bhi);
    __nv_bfloat16* blo = sym_addr_b(g_blo);

    cudaFuncSetAttribute(gemm_mma, cudaFuncAttributeMaxDynamicSharedMemorySize,
                         GEMM_SMEM);

    // 0) sincos LUT
    sincos_table_kernel<<<(T_ * 32) / 256, 256>>>(cost, sint);

    // 1) split x and w_qkv into bf16 hi/lo
    split_kernel<<<(M_ * D_ / 4) / 256, 256>>>(x, ahi, alo, M_ * D_ / 4);
    split_kernel<<<(3 * D_ * D_ / 4) / 256, 256>>>(w_qkv, bhi, blo, 3 * D_ * D_ / 4);

    // 2) qkv = x @ w_qkv^T  [16384, 3072]
    gemm_mma<<<dim3(3 * D_ / 128, M_ / 128), 256, GEMM_SMEM>>>(
        ahi, alo, bhi, blo, qkv, 3 * D_);

    // 3) RoPE + ELU feature map
    rope_feat_kernel<<<(PAIRS * T_ * 32) / 256, 256>>>(qkv, cost, sint, qf, kf);

    // 4) kv = K^T V and k_sum
    kv_ksum_kernel<<<dim3(NCHUNK, PAIRS), 256>>>(kf, qkv, kvprt, ksprt);
    reduce_kv_kernel<<<(PAIRS * HD_ * HD_) / 256, 256>>>(kvprt, ksprt, kv, ksum);

    // 5) out_head = (Q kv)/denom -> bf16 hi/lo directly (A of GEMM2)
    attn_out_kernel<<<dim3(T_ / 32, PAIRS), 256>>>(qf, kv, ksum, ahi, alo);

    // 6) split w_out, then out = attn @ w_out^T  [16384, 1024]
    split_kernel<<<(D_ * D_ / 4) / 256, 256>>>(w_out, bhi, blo, D_ * D_ / 4);
    gemm_mma<<<dim3(D_ / 128, M_ / 128), 256, GEMM_SMEM>>>(
        ahi, alo, bhi, blo, out, D_);
}

// round 9
// speedup vs baseline: 1.2407x; 1.0056x over previous
#include <cuda_runtime.h>
#include <cuda_bf16.h>
#include <math.h>
#include <stdint.h>

// ---------------------------------------------------------------------------
// LinearSelfAttention, Round 9: mma.sync bf16 hi/lo 3-pass GEMMs.
// = Round 6 GEMM (128x128, 8 warps, k16, 4-stage cp.async, RS=24)
// + pass-outermost MMA ordering (8 independent accumulators between
//   same-acc reuses -> hides HMMA latency).
// ---------------------------------------------------------------------------

#define B_   4
#define T_   4096
#define D_   1024
#define H_   16
#define HD_  64
#define M_   (B_ * T_)            // 16384
#define PAIRS (B_ * H_)           // 64
#define NCHUNK 16
#define ROWS_PER_CHUNK (T_ / NCHUNK)
#define GK 1024

// ------------------------- scratch (device globals) ------------------------
__device__ float g_qkv[(size_t)M_ * 3 * D_];
__device__ float g_qf[(size_t)PAIRS * T_ * HD_];
__device__ float g_kf[(size_t)PAIRS * T_ * HD_];
__device__ float g_kvpart[(size_t)NCHUNK * PAIRS * HD_ * HD_];
__device__ float g_kspart[(size_t)NCHUNK * PAIRS * HD_];
__device__ float g_kv[(size_t)PAIRS * HD_ * HD_];
__device__ float g_ksum[(size_t)PAIRS * HD_];
__device__ float g_cost[(size_t)T_ * 32];
__device__ float g_sint[(size_t)T_ * 32];
__device__ __nv_bfloat16 g_ahi[(size_t)M_ * D_];
__device__ __nv_bfloat16 g_alo[(size_t)M_ * D_];
__device__ __nv_bfloat16 g_bhi[(size_t)3 * D_ * D_];
__device__ __nv_bfloat16 g_blo[(size_t)3 * D_ * D_];

__constant__ float c_invfreq[32] = {
    1.0f, 0.7498942093324559f, 0.5623413251903491f, 0.4216965034285822f,
    0.31622776601683794f, 0.23713737056616552f, 0.1778279410038923f,
    0.13335214321633242f,
    0.1f, 0.07498942093324558f, 0.05623413251903491f, 0.04216965034285822f,
    0.03162277660168379f, 0.023713737056616554f, 0.01778279410038923f,
    0.013335214321633242f,
    0.01f, 0.007498942093324559f, 0.005623413251903491f, 0.004216965034285822f,
    0.0031622776601683794f, 0.0023713737056616554f, 0.001778279410038923f,
    0.0013335214321633242f,
    0.001f, 0.0007498942093324559f, 0.0005623413251903491f,
    0.0004216965034285822f, 0.00031622776601683794f, 0.00023713737056616554f,
    0.0001778279410038923f, 0.00013335214321633243f
};

// ------------------------- PTX helpers --------------------------------------
__device__ __forceinline__ uint32_t smem_u32(const void* p) {
    uint32_t a;
    asm("{ .reg .u64 t; cvta.to.shared.u64 t, %1; cvt.u32.u64 %0, t; }"
        : "=r"(a) : "l"(p));
    return a;
}
__device__ __forceinline__ void cpasync16(uint32_t s, const void* g) {
    asm volatile("cp.async.cg.shared.global [%0], [%1], 16;" :: "r"(s), "l"(g));
}
#define CP_COMMIT() asm volatile("cp.async.commit_group;" ::: "memory")
#define CP_WAIT2()  asm volatile("cp.async.wait_group 2;" ::: "memory")

__device__ __forceinline__ void ldsm4(uint32_t* r, uint32_t addr) {
    asm volatile("ldmatrix.sync.aligned.m8n8.x4.shared.b16 {%0,%1,%2,%3}, [%4];"
        : "=r"(r[0]), "=r"(r[1]), "=r"(r[2]), "=r"(r[3]) : "r"(addr));
}
__device__ __forceinline__ void mma16816(float* d, const uint32_t* a,
                                         const uint32_t* b) {
    asm volatile("mma.sync.aligned.m16n8k16.row.col.f32.bf16.bf16.f32 "
        "{%0,%1,%2,%3}, {%4,%5,%6,%7}, {%8,%9}, {%0,%1,%2,%3};"
        : "+f"(d[0]), "+f"(d[1]), "+f"(d[2]), "+f"(d[3])
        : "r"(a[0]), "r"(a[1]), "r"(a[2]), "r"(a[3]), "r"(b[0]), "r"(b[1]));
}

// ------------------------- MMA GEMM: C = A * B^T ----------------------------
// Block 128x128, 8 warps (4M x 2N), warp tile 32x64, K-step 16, 4 stages.
#define RS 24
#define OPB (128 * RS * 2)            // 6144 B per operand tile
#define STAGE_B (4 * OPB)             // 24576 B per stage
#define NSTAGE 4
#define GEMM_SMEM (NSTAGE * STAGE_B)  // 98304 B  -> 2 CTAs/SM

__global__ void __launch_bounds__(256, 2)
gemm_mma(const __nv_bfloat16* __restrict__ Ahi, const __nv_bfloat16* __restrict__ Alo,
         const __nv_bfloat16* __restrict__ Bhi, const __nv_bfloat16* __restrict__ Blo,
         float* __restrict__ C, int N)
{
    extern __shared__ __nv_bfloat16 smem[];

    const int tid = threadIdx.x;
    const int l = tid & 31;
    const int w = tid >> 5;
    const int mw = w >> 1;                 // 0..3
    const int nw = w & 1;                  // 0..1
    const long rowA0 = (long)blockIdx.y * 128;
    const long rowB0 = (long)blockIdx.x * 128;

    // ---- loader: each thread copies 16B per operand per stage -------------
    const int lrow = tid >> 1;             // 0..127
    const int lhalf = (tid & 1) * 8;       // 0 or 8 (bf16 elems)
    const __nv_bfloat16* gsrc[4] = {
        Ahi + (rowA0 + lrow) * GK + lhalf,
        Alo + (rowA0 + lrow) * GK + lhalf,
        Bhi + (rowB0 + lrow) * GK + lhalf,
        Blo + (rowB0 + lrow) * GK + lhalf };
    const uint32_t sbase = smem_u32(&smem[0]);
    const uint32_t soff = (uint32_t)((lrow * RS + lhalf) * 2);   // 16B aligned

    float acc[2][8][4];
    #pragma unroll
    for (int i = 0; i < 2; i++)
        #pragma unroll
        for (int j = 0; j < 8; j++)
            #pragma unroll
            for (int k = 0; k < 4; k++) acc[i][j][k] = 0.0f;

    // ldmatrix offsets within a stage
    const uint32_t aoffA = (uint32_t)(((mw * 32 + (l & 15)) * RS + (l >> 4) * 8) * 2);
    const uint32_t aoffB = (uint32_t)((((nw * 64 + (l & 7) + ((l >> 4) << 3)) * RS
                                       + ((l >> 3) & 1) * 8)) * 2);

    const int NIT = GK / 16;               // 64

    // ---- prefetch stages 0..2 ---------------------------------------------
    #pragma unroll
    for (int s = 0; s < NSTAGE - 1; s++) {
        const uint32_t dst = sbase + s * STAGE_B;
        #pragma unroll
        for (int o = 0; o < 4; o++)
            cpasync16(dst + o * OPB + soff, gsrc[o] + s * 16);
        CP_COMMIT();
    }

    for (int c = 0; c < NIT; c++) {
        CP_WAIT2();                        // stage c resident
        __syncthreads();                   // slot (c-1)%4 free for refill

        const int pf = c + NSTAGE - 1;
        if (pf < NIT) {
            const uint32_t dst = sbase + (pf & (NSTAGE - 1)) * STAGE_B;
            #pragma unroll
            for (int o = 0; o < 4; o++)
                cpasync16(dst + o * OPB + soff, gsrc[o] + pf * 16);
        }
        CP_COMMIT();                       // unconditional: pending stays == 3

        const uint32_t stb = sbase + (c & (NSTAGE - 1)) * STAGE_B;

        // load all fragments for this k16 first
        uint32_t ah[2][4], al[2][4];
        #pragma unroll
        for (int mt = 0; mt < 2; mt++) {
            uint32_t ao = stb + aoffA + (uint32_t)(mt * 16 * RS * 2);
            ldsm4(ah[mt], ao);
            ldsm4(al[mt], ao + OPB);
        }
        uint32_t bh[8][2], bl[8][2];
        #pragma unroll
        for (int hf = 0; hf < 2; hf++)
            #pragma unroll
            for (int nt2 = 0; nt2 < 2; nt2++) {
                uint32_t bo = stb + aoffB
                            + (uint32_t)((hf * 32 + nt2 * 16) * RS * 2) + 2 * OPB;
                uint32_t r[4];
                int nb = hf * 4 + nt2 * 2;
                ldsm4(r, bo);
                bh[nb][0] = r[0]; bh[nb][1] = r[1];
                bh[nb + 1][0] = r[2]; bh[nb + 1][1] = r[3];
                ldsm4(r, bo + OPB);
                bl[nb][0] = r[0]; bl[nb][1] = r[1];
                bl[nb + 1][0] = r[2]; bl[nb + 1][1] = r[3];
            }

        // pass-outermost: 16 independent MMAs per pass before any acc reuse
        #pragma unroll
        for (int mt = 0; mt < 2; mt++)
            #pragma unroll
            for (int nt = 0; nt < 8; nt++)
                mma16816(acc[mt][nt], ah[mt], bh[nt]);
        #pragma unroll
        for (int mt = 0; mt < 2; mt++)
            #pragma unroll
            for (int nt = 0; nt < 8; nt++)
                mma16816(acc[mt][nt], ah[mt], bl[nt]);
        #pragma unroll
        for (int mt = 0; mt < 2; mt++)
            #pragma unroll
            for (int nt = 0; nt < 8; nt++)
                mma16816(acc[mt][nt], al[mt], bh[nt]);
    }

    // ---- epilogue ----------------------------------------------------------
    const long ccol0 = rowB0 + nw * 64 + 2 * (l & 3);
    #pragma unroll
    for (int mt = 0; mt < 2; mt++) {
        const long row = rowA0 + mw * 32 + mt * 16 + (l >> 2);
        #pragma unroll
        for (int nt = 0; nt < 8; nt++) {
            const float* d = acc[mt][nt];
            long col = ccol0 + nt * 8;
            *(float2*)(C + row * N + col) = make_float2(d[0], d[1]);
            *(float2*)(C + (row + 8) * N + col) = make_float2(d[2], d[3]);
        }
    }
}

// ------------------------- fp32 -> bf16 hi/lo split -------------------------
__global__ void __launch_bounds__(256)
split_kernel(const float* __restrict__ src, __nv_bfloat16* __restrict__ hi,
             __nv_bfloat16* __restrict__ lo, int n4)
{
    int i = blockIdx.x * blockDim.x + threadIdx.x;
    if (i >= n4) return;
    float4 v = ((const float4*)src)[i];
    union { __nv_bfloat16 b[4]; uint2 u; } Hv, Lv;
    float f[4] = {v.x, v.y, v.z, v.w};
    #pragma unroll
    for (int j = 0; j < 4; j++) {
        __nv_bfloat16 h = __float2bfloat16(f[j]);
        Hv.b[j] = h;
        Lv.b[j] = __float2bfloat16(f[j] - __bfloat162float(h));
    }
    ((uint2*)hi)[i] = Hv.u;
    ((uint2*)lo)[i] = Lv.u;
}

// ------------------------- sincos table -------------------------------------
__global__ void __launch_bounds__(256)
sincos_table_kernel(float* __restrict__ cost, float* __restrict__ sint)
{
    int idx = blockIdx.x * blockDim.x + threadIdx.x;   // T*32
    int t = idx >> 5;
    int i = idx & 31;
    float s, c;
    sincosf((float)t * c_invfreq[i], &s, &c);
    cost[idx] = c;
    sint[idx] = s;
}

// ------------------------- RoPE + feature map -------------------------------
__global__ void __launch_bounds__(256)
rope_feat_kernel(const float* __restrict__ qkv,
                 const float* __restrict__ cost, const float* __restrict__ sint,
                 float* __restrict__ qf, float* __restrict__ kf)
{
    int idx = blockIdx.x * blockDim.x + threadIdx.x;
    int i = idx & 31;
    int t = (idx >> 5) & (T_ - 1);
    int pair = idx >> 17;
    int b = pair >> 4;
    int h = pair & 15;

    size_t basei = ((size_t)(b * T_ + t)) * (3 * D_) + h * HD_;
    float qe = qkv[basei + i];
    float qo = qkv[basei + i + 32];
    float ke = qkv[basei + D_ + i];
    float ko = qkv[basei + D_ + i + 32];

    float c = cost[t * 32 + i];
    float s = sint[t * 32 + i];

    float qre = qe * c - qo * s;
    float qro = qe * s + qo * c;
    float kre = ke * c - ko * s;
    float kro = ke * s + ko * c;

    const float scale = 0.125f;
    qre *= scale; qro *= scale;

    float fqe = qre > 0.0f ? qre + 1.0f : expm1f(qre) + 1.0f;
    float fqo = qro > 0.0f ? qro + 1.0f : expm1f(qro) + 1.0f;
    float fke = kre > 0.0f ? kre + 1.0f : expm1f(kre) + 1.0f;
    float fko = kro > 0.0f ? kro + 1.0f : expm1f(kro) + 1.0f;

    size_t ob = ((size_t)pair * T_ + t) * HD_;
    qf[ob + i]      = fqe;
    qf[ob + i + 32] = fqo;
    kf[ob + i]      = fke;
    kf[ob + i + 32] = fko;
}

// ------------------------- kv = K^T V, k_sum (partials) ---------------------
__global__ void __launch_bounds__(256)
kv_ksum_kernel(const float* __restrict__ kf, const float* __restrict__ qkv,
               float* __restrict__ kvpart, float* __restrict__ kspart)
{
    __shared__ float ks[32][64];
    __shared__ float vs[32][64];

    const int pair = blockIdx.y;
    const int chunk = blockIdx.x;
    const int b = pair >> 4;
    const int h = pair & 15;
    const int tid = threadIdx.x;
    const int tx = tid & 15;
    const int ty = tid >> 4;

    const float* kbase = kf + ((size_t)pair * T_ + chunk * ROWS_PER_CHUNK) * HD_;
    const float* vbase = qkv + ((size_t)(b * T_ + chunk * ROWS_PER_CHUNK)) * (3 * D_)
                         + 2 * D_ + h * HD_;

    float acc[4][4];
    #pragma unroll
    for (int i = 0; i < 4; i++)
        #pragma unroll
        for (int j = 0; j < 4; j++) acc[i][j] = 0.0f;
    float ksl[4] = {0.0f, 0.0f, 0.0f, 0.0f};

    for (int tile = 0; tile < ROWS_PER_CHUNK / 32; tile++) {
        #pragma unroll
        for (int lp = 0; lp < 2; lp++) {
            int fi = tid + lp * 256;
            int row = fi >> 4;
            int c4 = (fi & 15) * 4;
            *(float4*)&ks[row][c4] =
                *(const float4*)(kbase + (size_t)(tile * 32 + row) * HD_ + c4);
            *(float4*)&vs[row][c4] =
                *(const float4*)(vbase + (size_t)(tile * 32 + row) * (3 * D_) + c4);
        }
        __syncthreads();

        #pragma unroll
        for (int r = 0; r < 32; r++) {
            float ka[4], va[4];
            *(float4*)ka = *(const float4*)&ks[r][ty * 4];
            *(float4*)va = *(const float4*)&vs[r][tx * 4];
            #pragma unroll
            for (int i = 0; i < 4; i++)
                #pragma unroll
                for (int j = 0; j < 4; j++)
                    acc[i][j] = fmaf(ka[i], va[j], acc[i][j]);
            if (ty == 0) {
                #pragma unroll
                for (int j = 0; j < 4; j++)
                    ksl[j] += ks[r][tx * 4 + j];
            }
        }
        __syncthreads();
    }

    float* kvp = kvpart + (size_t)chunk * (PAIRS * HD_ * HD_) + (size_t)pair * HD_ * HD_;
    #pragma unroll
    for (int i = 0; i < 4; i++)
        #pragma unroll
        for (int j = 0; j < 4; j++)
            kvp[(ty * 4 + i) * HD_ + tx * 4 + j] = acc[i][j];
    if (ty == 0) {
        float* ksp = kspart + (size_t)chunk * (PAIRS * HD_) + pair * HD_;
        #pragma unroll
        for (int j = 0; j < 4; j++) ksp[tx * 4 + j] = ksl[j];
    }
}

__global__ void __launch_bounds__(256)
reduce_kv_kernel(const float* __restrict__ kvpart, const float* __restrict__ kspart,
                 float* __restrict__ kv, float* __restrict__ ksum)
{
    int i = blockIdx.x * blockDim.x + threadIdx.x;
    float s = 0.0f;
    #pragma unroll
    for (int c = 0; c < NCHUNK; c++)
        s += kvpart[(size_t)c * (PAIRS * HD_ * HD_) + i];
    kv[i] = s;
    if (i < PAIRS * HD_) {
        float s2 = 0.0f;
        #pragma unroll
        for (int c = 0; c < NCHUNK; c++)
            s2 += kspart[(size_t)c * (PAIRS * HD_) + i];
        ksum[i] = s2;
    }
}

// ---------------- out = (Q kv)/denom, fused bf16 hi/lo output ---------------
__global__ void __launch_bounds__(256)
attn_out_kernel(const float* __restrict__ qf, const float* __restrict__ kv,
                const float* __restrict__ ksum,
                __nv_bfloat16* __restrict__ ahi, __nv_bfloat16* __restrict__ alo)
{
    __shared__ float kv_s[HD_][HD_];
    __shared__ float q_s[32][HD_];
    __shared__ float ksum_s[HD_];

    const int pair = blockIdx.y;
    const int t0 = blockIdx.x * 32;
    const int b = pair >> 4;
    const int h = pair & 15;
    const int tid = threadIdx.x;
    const int row = tid >> 3;
    const int tx = tid & 7;

    const float4* kvp = (const float4*)(kv + (size_t)pair * HD_ * HD_);
    #pragma unroll
    for (int lp = 0; lp < 4; lp++)
        ((float4*)kv_s)[tid + lp * 256] = kvp[tid + lp * 256];
    if (tid < 16)
        ((float4*)ksum_s)[tid] = ((const float4*)(ksum + pair * HD_))[tid];
    const float4* qp = (const float4*)(qf + ((size_t)pair * T_ + t0) * HD_);
    #pragma unroll
    for (int lp = 0; lp < 2; lp++)
        ((float4*)q_s)[tid + lp * 256] = qp[tid + lp * 256];
    __syncthreads();

    float acc[8] = {0, 0, 0, 0, 0, 0, 0, 0};
    float den = 0.0f;
    #pragma unroll
    for (int d = 0; d < HD_; d++) {
        float qd = q_s[row][d];
        den = fmaf(qd, ksum_s[d], den);
        float4 k0 = *(const float4*)&kv_s[d][tx * 8];
        float4 k1 = *(const float4*)&kv_s[d][tx * 8 + 4];
        acc[0] = fmaf(qd, k0.x, acc[0]);
        acc[1] = fmaf(qd, k0.y, acc[1]);
        acc[2] = fmaf(qd, k0.z, acc[2]);
        acc[3] = fmaf(qd, k0.w, acc[3]);
        acc[4] = fmaf(qd, k1.x, acc[4]);
        acc[5] = fmaf(qd, k1.y, acc[5]);
        acc[6] = fmaf(qd, k1.z, acc[6]);
        acc[7] = fmaf(qd, k1.w, acc[7]);
    }
    float inv = 1.0f / fmaxf(den, 1e-6f);

    union { __nv_bfloat16 b[8]; uint4 u; } Hv, Lv;
    #pragma unroll
    for (int j = 0; j < 8; j++) {
        float v = acc[j] * inv;
        __nv_bfloat16 hh = __float2bfloat16(v);
        Hv.b[j] = hh;
        Lv.b[j] = __float2bfloat16(v - __bfloat162float(hh));
    }
    size_t off = ((size_t)(b * T_ + t0 + row)) * D_ + h * HD_ + tx * 8;
    *(uint4*)(ahi + off) = Hv.u;
    *(uint4*)(alo + off) = Lv.u;
}

// ------------------------- launch ------------------------------------------
static float* sym_addr_f(const void* symbol)
{
    void* p = nullptr;
    cudaGetSymbolAddress(&p, symbol);
    return (float*)p;
}
static __nv_bfloat16* sym_addr_b(const void* symbol)
{
    void* p = nullptr;
    cudaGetSymbolAddress(&p, symbol);
    return (__nv_bfloat16*)p;
}

extern "C" void kernel_launch(void* const* d_in, const int* in_sizes, int n_in,
                              void* d_out, int out_size)
{
    (void)in_sizes; (void)n_in; (void)out_size;
    const float* x     = (const float*)d_in[0];   // [B,T,D]
    const float* w_qkv = (const float*)d_in[1];   // [3D,D]
    const float* w_out = (const float*)d_in[2];   // [D,D]
    float* out = (float*)d_out;                   // [B,T,D]

    float* qkv   = sym_addr_f(g_qkv);
    float* qf    = sym_addr_f(g_qf);
    float* kf    = sym_addr_f(g_kf);
    float* kvprt = sym_addr_f(g_kvpart);
    float* ksprt = sym_addr_f(g_kspart);
    float* kv    = sym_addr_f(g_kv);
    float* ksum  = sym_addr_f(g_ksum);
    float* cost  = sym_addr_f(g_cost);
    float* sint  = sym_addr_f(g_sint);
    __nv_bfloat16* ahi = sym_addr_b(g_ahi);
    __nv_bfloat16* alo = sym_addr_b(g_alo);
    __nv_bfloat16* bhi = sym_addr_b(g_bhi);
    __nv_bfloat16* blo = sym_addr_b(g_blo);

    cudaFuncSetAttribute(gemm_mma, cudaFuncAttributeMaxDynamicSharedMemorySize,
                         GEMM_SMEM);

    // 0) sincos LUT
    sincos_table_kernel<<<(T_ * 32) / 256, 256>>>(cost, sint);

    // 1) split x and w_qkv into bf16 hi/lo
    split_kernel<<<(M_ * D_ / 4) / 256, 256>>>(x, ahi, alo, M_ * D_ / 4);
    split_kernel<<<(3 * D_ * D_ / 4) / 256, 256>>>(w_qkv, bhi, blo, 3 * D_ * D_ / 4);

    // 2) qkv = x @ w_qkv^T  [16384, 3072]
    gemm_mma<<<dim3(3 * D_ / 128, M_ / 128), 256, GEMM_SMEM>>>(
        ahi, alo, bhi, blo, qkv, 3 * D_);

    // 3) RoPE + ELU feature map
    rope_feat_kernel<<<(PAIRS * T_ * 32) / 256, 256>>>(qkv, cost, sint, qf, kf);

    // 4) kv = K^T V and k_sum
    kv_ksum_kernel<<<dim3(NCHUNK, PAIRS), 256>>>(kf, qkv, kvprt, ksprt);
    reduce_kv_kernel<<<(PAIRS * HD_ * HD_) / 256, 256>>>(kvprt, ksprt, kv, ksum);

    // 5) out_head = (Q kv)/denom -> bf16 hi/lo directly (A of GEMM2)
    attn_out_kernel<<<dim3(T_ / 32, PAIRS), 256>>>(qf, kv, ksum, ahi, alo);

    // 6) split w_out, then out = attn @ w_out^T  [16384, 1024]
    split_kernel<<<(D_ * D_ / 4) / 256, 256>>>(w_out, bhi, blo, D_ * D_ / 4);
    gemm_mma<<<dim3(D_ / 128, M_ / 128), 256, GEMM_SMEM>>>(
        ahi, alo, bhi, blo, out, D_);
}